// round 5
// baseline (speedup 1.0000x reference)
#include <cuda_runtime.h>
#include <cuda_fp16.h>
#include <cstdint>

#define NN 100000
#define EE 1600000
#define DD 64
#define NB 98            // ceil(NN/1024)
#define GEMM_BLOCKS 782  // ceil(NN/128)
#define DEG_BLOCKS 1563  // ceil(EE/1024), 4 edges/thread

// ---------------- device scratch (zero-initialized at module load) ----------
__device__ int    g_degi[NN];      // in-degree; reset by gather for next call
__device__ int    g_start[NN];
__device__ float  g_dinv[NN];
__device__ float  g_invdeg[NN];
__device__ int    g_rank[EE];
__device__ int    g_csr[EE];
__device__ __half2 g_yh[NN * 32];  // y = x @ W^T in fp16 (row-major, 32 half2/row)
__device__ unsigned long long g_state[NB];
__device__ int    g_ticket;

// ---------------------------------------------------------------------------
__device__ __forceinline__ unsigned f2tf32(float f) {
    unsigned u;
    asm("cvt.rna.tf32.f32 %0, %1;" : "=r"(u) : "f"(f));
    return u;
}

__device__ __forceinline__ void mma_tf32(float acc[4], unsigned a0, unsigned a1,
                                         unsigned a2, unsigned a3,
                                         unsigned b0, unsigned b1) {
    asm volatile(
        "mma.sync.aligned.m16n8k8.row.col.f32.tf32.tf32.f32 "
        "{%0,%1,%2,%3}, {%4,%5,%6,%7}, {%8,%9}, {%0,%1,%2,%3};"
        : "+f"(acc[0]), "+f"(acc[1]), "+f"(acc[2]), "+f"(acc[3])
        : "r"(a0), "r"(a1), "r"(a2), "r"(a3), "r"(b0), "r"(b1));
}

// Fused: blocks [0,GEMM_BLOCKS): y = x @ W^T (tf32 MMA, fp16 store)
//        blocks [GEMM_BLOCKS,+DEG_BLOCKS): degree histogram + rank capture.
//        First deg block also re-arms the scan state for this call.
__global__ __launch_bounds__(256) void fused_gemm_deg_kernel(
        const float* __restrict__ W, const float* __restrict__ x,
        const int* __restrict__ col) {
    __shared__ unsigned sW[64 * 68];
    int tid = threadIdx.x;

    if (blockIdx.x >= GEMM_BLOCKS) {
        int dblk = blockIdx.x - GEMM_BLOCKS;
        if (dblk == 0) {                 // re-arm scan state (ordered by kernel boundary)
            if (tid < NB) g_state[tid] = 0ULL;
            if (tid == NB) g_ticket = 0;
        }
        int base = dblk * 1024;
        #pragma unroll
        for (int u = 0; u < 4; u++) {
            int e = base + u * 256 + tid;
            if (e < EE) g_rank[e] = atomicAdd(&g_degi[col[e]], 1);
        }
        return;
    }

    #pragma unroll
    for (int t = tid; t < 4096; t += 256) {
        int n = t >> 6, k = t & 63;
        sW[n * 68 + k] = f2tf32(W[t]);
    }
    __syncthreads();

    int warp = tid >> 5, lane = tid & 31;
    int gid = lane >> 2, tg = lane & 3;
    int r0 = blockIdx.x * 128 + warp * 16;
    int rA = r0 + gid;
    int rB = rA + 8;
    int rAc = rA < NN ? rA : NN - 1;
    int rBc = rB < NN ? rB : NN - 1;
    const float* pA = x + rAc * 64 + tg;
    const float* pB = x + rBc * 64 + tg;

    float acc[8][4];
    #pragma unroll
    for (int n = 0; n < 8; n++)
        #pragma unroll
        for (int j = 0; j < 4; j++) acc[n][j] = 0.0f;

    #pragma unroll
    for (int s = 0; s < 8; s++) {
        int k0 = s * 8;
        unsigned a0 = f2tf32(pA[k0]);
        unsigned a1 = f2tf32(pB[k0]);
        unsigned a2 = f2tf32(pA[k0 + 4]);
        unsigned a3 = f2tf32(pB[k0 + 4]);
        #pragma unroll
        for (int n = 0; n < 8; n++) {
            unsigned b0 = sW[(n * 8 + gid) * 68 + k0 + tg];
            unsigned b1 = sW[(n * 8 + gid) * 68 + k0 + tg + 4];
            mma_tf32(acc[n], a0, a1, a2, a3, b0, b1);
        }
    }

    #pragma unroll
    for (int n = 0; n < 8; n++) {
        int cidx = n * 4 + tg;
        if (rA < NN) g_yh[rA * 32 + cidx] = __floats2half2_rn(acc[n][0], acc[n][1]);
        if (rB < NN) g_yh[rB * 32 + cidx] = __floats2half2_rn(acc[n][2], acc[n][3]);
    }
}

// ---------------------------------------------------------------------------
// Single-pass decoupled-lookback scan + finalize dinv/invdeg.
__global__ void scan_kernel() {
    __shared__ int wsum[32];
    __shared__ int sh_tile;
    __shared__ int sh_prefix;
    int tid = threadIdx.x, lane = tid & 31, wid = tid >> 5;

    if (tid == 0) sh_tile = atomicAdd(&g_ticket, 1);
    __syncthreads();
    int tile = sh_tile;
    int i = tile * 1024 + tid;
    int v = (i < NN) ? g_degi[i] : 0;

    int xs = v;
    #pragma unroll
    for (int d = 1; d < 32; d <<= 1) {
        int t = __shfl_up_sync(0xffffffffu, xs, d);
        if (lane >= d) xs += t;
    }
    if (lane == 31) wsum[wid] = xs;
    __syncthreads();
    if (wid == 0) {
        int s = wsum[lane];
        #pragma unroll
        for (int d = 1; d < 32; d <<= 1) {
            int t = __shfl_up_sync(0xffffffffu, s, d);
            if (lane >= d) s += t;
        }
        wsum[lane] = s;
    }
    __syncthreads();
    int incl = xs + (wid ? wsum[wid - 1] : 0);
    int total = wsum[31];

    if (tid == 0) {
        unsigned long long pack =
            ((unsigned long long)(tile == 0 ? 2u : 1u) << 32) | (unsigned)total;
        atomicExch(&g_state[tile], pack);
    }

    if (wid == 0) {
        int prefix = 0;
        if (tile > 0) {
            int base = tile - 1;
            while (true) {
                int t = base - lane;
                unsigned long long s;
                if (t >= 0) {
                    do { s = atomicAdd(&g_state[t], 0ULL); } while ((unsigned)(s >> 32) == 0u);
                } else {
                    s = (2ULL << 32);
                }
                unsigned flag = (unsigned)(s >> 32);
                int val = (int)(unsigned)s;
                unsigned ball = __ballot_sync(0xffffffffu, flag == 2u);
                int firstInc = __ffs(ball) - 1;
                int contrib = ball ? ((lane <= firstInc) ? val : 0) : val;
                #pragma unroll
                for (int d = 16; d; d >>= 1)
                    contrib += __shfl_xor_sync(0xffffffffu, contrib, d);
                prefix += contrib;
                if (ball) break;
                base -= 32;
            }
            if (lane == 0)
                atomicExch(&g_state[tile],
                           (2ULL << 32) | (unsigned)(prefix + total));
        }
        if (lane == 0) sh_prefix = prefix;
    }
    __syncthreads();
    int prefix = sh_prefix;
    if (i < NN) {
        g_start[i] = prefix + incl - v;
        float df = (float)v + 1.0f;
        g_dinv[i]   = rsqrtf(df);
        g_invdeg[i] = 1.0f / df;
    }
}

// ---------------------------------------------------------------------------
// bin: atomic-free CSR placement using precomputed ranks. 4 edges/thread.
__global__ __launch_bounds__(256) void bin_kernel(const int* __restrict__ row,
                                                  const int* __restrict__ col) {
    int base = blockIdx.x * 1024;
    #pragma unroll
    for (int u = 0; u < 4; u++) {
        int e = base + u * 256 + threadIdx.x;
        if (e < EE) {
            int c = col[e];
            g_csr[g_start[c] + g_rank[e]] = row[e];
        }
    }
}

// ---------------------------------------------------------------------------
// gather: one warp per target node. Warp stages {src, w} for up to 32 incoming
// edges (coalesced csr read), then streams coalesced 128B fp16 y-rows.
// Lane owns output columns 2*lid, 2*lid+1. Also resets g_degi for next call.
#define GW 8
__global__ __launch_bounds__(256) void gather_kernel(const float* __restrict__ bias,
                                                     float2* __restrict__ out2) {
    __shared__ int   ssrc[GW][32];
    __shared__ float sw[GW][32];
    int lid = threadIdx.x & 31, wid = threadIdx.x >> 5;
    int c = blockIdx.x * GW + wid;
    if (c >= NN) return;

    int start = g_start[c];
    int cnt   = g_degi[c];
    if (lid == 0) g_degi[c] = 0;       // re-arm for next call

    float2 acc = make_float2(0.f, 0.f);
    for (int k0 = 0; k0 < cnt; k0 += 32) {
        int m = cnt - k0; if (m > 32) m = 32;
        if (lid < m) {
            int src = g_csr[start + k0 + lid];
            ssrc[wid][lid] = src;
            sw[wid][lid]   = g_dinv[src];
        }
        __syncwarp();
        #pragma unroll 4
        for (int t = 0; t < m; t++) {
            int   r = ssrc[wid][t];
            float w = sw[wid][t];
            float2 v = __half22float2(g_yh[r * 32 + lid]);
            acc.x += w * v.x;
            acc.y += w * v.y;
        }
        __syncwarp();
    }

    float dc  = g_dinv[c];
    float inv = g_invdeg[c];
    float2 self = __half22float2(g_yh[c * 32 + lid]);
    float2 b = ((const float2*)bias)[lid];

    float2 o;
    o.x = dc * acc.x + inv * self.x + b.x;
    o.y = dc * acc.y + inv * self.y + b.y;
    out2[c * 32 + lid] = o;
}

// ---------------------------------------------------------------------------
extern "C" void kernel_launch(void* const* d_in, const int* in_sizes, int n_in,
                              void* d_out, int out_size) {
    const float* x  = nullptr;
    const int*   ei = nullptr;
    const float* Ww = nullptr;
    const float* Wb = nullptr;
    for (int i = 0; i < n_in; i++) {
        int sz = in_sizes[i];
        if (sz == 2 * EE)             ei = (const int*)d_in[i];
        else if (sz == DD * DD)       Ww = (const float*)d_in[i];
        else if (sz == DD)            Wb = (const float*)d_in[i];
        else if (sz == NN * DD && !x) x  = (const float*)d_in[i];
    }
    const int* row = ei;          // sources
    const int* col = ei + EE;     // targets
    float2* out2 = (float2*)d_out;

    fused_gemm_deg_kernel<<<GEMM_BLOCKS + DEG_BLOCKS, 256>>>(Ww, x, col);
    scan_kernel          <<<NB, 1024>>>();
    bin_kernel           <<<DEG_BLOCKS, 256>>>(row, col);
    gather_kernel        <<<(NN + GW - 1) / GW, 256>>>(Wb, out2);
}

// round 6
// speedup vs baseline: 1.8129x; 1.8129x over previous
#include <cuda_runtime.h>
#include <cuda_fp16.h>
#include <cstdint>

#define NN 100000
#define EE 1600000
#define DD 64
#define NB 98            // ceil(NN/1024)
#define GEMM_BLOCKS 782  // ceil(NN/128)
#define DEG_BLOCKS 1563  // ceil(EE/1024), 4 edges/thread

// ---------------- device scratch (zero-initialized at module load) ----------
__device__ int    g_degi[NN];      // in-degree; reset by gather for next call
__device__ int    g_start[NN];
__device__ float  g_dinv[NN];
__device__ float  g_invdeg[NN];
__device__ int    g_rank[EE];
__device__ int    g_csr[EE];
__device__ __half2 g_yh[NN * 32];  // y = x @ W^T in fp16 (row-major)
__device__ unsigned long long g_state[NB];
__device__ int    g_ticket;

// ---------------------------------------------------------------------------
__device__ __forceinline__ unsigned f2tf32(float f) {
    unsigned u;
    asm("cvt.rna.tf32.f32 %0, %1;" : "=r"(u) : "f"(f));
    return u;
}

__device__ __forceinline__ void mma_tf32(float acc[4], unsigned a0, unsigned a1,
                                         unsigned a2, unsigned a3,
                                         unsigned b0, unsigned b1) {
    asm volatile(
        "mma.sync.aligned.m16n8k8.row.col.f32.tf32.tf32.f32 "
        "{%0,%1,%2,%3}, {%4,%5,%6,%7}, {%8,%9}, {%0,%1,%2,%3};"
        : "+f"(acc[0]), "+f"(acc[1]), "+f"(acc[2]), "+f"(acc[3])
        : "r"(a0), "r"(a1), "r"(a2), "r"(a3), "r"(b0), "r"(b1));
}

// Fused: blocks [0,GEMM_BLOCKS): y = x @ W^T (tf32 MMA, fp16 store)
//        blocks [GEMM_BLOCKS,+DEG_BLOCKS): degree histogram + rank capture.
//        First deg block re-arms the scan state for this call.
__global__ __launch_bounds__(256) void fused_gemm_deg_kernel(
        const float* __restrict__ W, const float* __restrict__ x,
        const int* __restrict__ col) {
    __shared__ unsigned sW[64 * 68];
    int tid = threadIdx.x;

    if (blockIdx.x >= GEMM_BLOCKS) {
        int dblk = blockIdx.x - GEMM_BLOCKS;
        if (dblk == 0) {
            if (tid < NB) g_state[tid] = 0ULL;
            if (tid == NB) g_ticket = 0;
        }
        int base = dblk * 1024;
        #pragma unroll
        for (int u = 0; u < 4; u++) {
            int e = base + u * 256 + tid;
            if (e < EE) g_rank[e] = atomicAdd(&g_degi[col[e]], 1);
        }
        return;
    }

    #pragma unroll
    for (int t = tid; t < 4096; t += 256) {
        int n = t >> 6, k = t & 63;
        sW[n * 68 + k] = f2tf32(W[t]);
    }
    __syncthreads();

    int warp = tid >> 5, lane = tid & 31;
    int gid = lane >> 2, tg = lane & 3;
    int r0 = blockIdx.x * 128 + warp * 16;
    int rA = r0 + gid;
    int rB = rA + 8;
    int rAc = rA < NN ? rA : NN - 1;
    int rBc = rB < NN ? rB : NN - 1;
    const float* pA = x + rAc * 64 + tg;
    const float* pB = x + rBc * 64 + tg;

    float acc[8][4];
    #pragma unroll
    for (int n = 0; n < 8; n++)
        #pragma unroll
        for (int j = 0; j < 4; j++) acc[n][j] = 0.0f;

    #pragma unroll
    for (int s = 0; s < 8; s++) {
        int k0 = s * 8;
        unsigned a0 = f2tf32(pA[k0]);
        unsigned a1 = f2tf32(pB[k0]);
        unsigned a2 = f2tf32(pA[k0 + 4]);
        unsigned a3 = f2tf32(pB[k0 + 4]);
        #pragma unroll
        for (int n = 0; n < 8; n++) {
            unsigned b0 = sW[(n * 8 + gid) * 68 + k0 + tg];
            unsigned b1 = sW[(n * 8 + gid) * 68 + k0 + tg + 4];
            mma_tf32(acc[n], a0, a1, a2, a3, b0, b1);
        }
    }

    #pragma unroll
    for (int n = 0; n < 8; n++) {
        int cidx = n * 4 + tg;
        if (rA < NN) g_yh[rA * 32 + cidx] = __floats2half2_rn(acc[n][0], acc[n][1]);
        if (rB < NN) g_yh[rB * 32 + cidx] = __floats2half2_rn(acc[n][2], acc[n][3]);
    }
}

// ---------------------------------------------------------------------------
// Single-pass decoupled-lookback scan + finalize dinv/invdeg.
__global__ void scan_kernel() {
    __shared__ int wsum[32];
    __shared__ int sh_tile;
    __shared__ int sh_prefix;
    int tid = threadIdx.x, lane = tid & 31, wid = tid >> 5;

    if (tid == 0) sh_tile = atomicAdd(&g_ticket, 1);
    __syncthreads();
    int tile = sh_tile;
    int i = tile * 1024 + tid;
    int v = (i < NN) ? g_degi[i] : 0;

    int xs = v;
    #pragma unroll
    for (int d = 1; d < 32; d <<= 1) {
        int t = __shfl_up_sync(0xffffffffu, xs, d);
        if (lane >= d) xs += t;
    }
    if (lane == 31) wsum[wid] = xs;
    __syncthreads();
    if (wid == 0) {
        int s = wsum[lane];
        #pragma unroll
        for (int d = 1; d < 32; d <<= 1) {
            int t = __shfl_up_sync(0xffffffffu, s, d);
            if (lane >= d) s += t;
        }
        wsum[lane] = s;
    }
    __syncthreads();
    int incl = xs + (wid ? wsum[wid - 1] : 0);
    int total = wsum[31];

    if (tid == 0) {
        unsigned long long pack =
            ((unsigned long long)(tile == 0 ? 2u : 1u) << 32) | (unsigned)total;
        atomicExch(&g_state[tile], pack);
    }

    if (wid == 0) {
        int prefix = 0;
        if (tile > 0) {
            int base = tile - 1;
            while (true) {
                int t = base - lane;
                unsigned long long s;
                if (t >= 0) {
                    do { s = atomicAdd(&g_state[t], 0ULL); } while ((unsigned)(s >> 32) == 0u);
                } else {
                    s = (2ULL << 32);
                }
                unsigned flag = (unsigned)(s >> 32);
                int val = (int)(unsigned)s;
                unsigned ball = __ballot_sync(0xffffffffu, flag == 2u);
                int firstInc = __ffs(ball) - 1;
                int contrib = ball ? ((lane <= firstInc) ? val : 0) : val;
                #pragma unroll
                for (int d = 16; d; d >>= 1)
                    contrib += __shfl_xor_sync(0xffffffffu, contrib, d);
                prefix += contrib;
                if (ball) break;
                base -= 32;
            }
            if (lane == 0)
                atomicExch(&g_state[tile],
                           (2ULL << 32) | (unsigned)(prefix + total));
        }
        if (lane == 0) sh_prefix = prefix;
    }
    __syncthreads();
    int prefix = sh_prefix;
    if (i < NN) {
        g_start[i] = prefix + incl - v;
        float df = (float)v + 1.0f;
        g_dinv[i]   = rsqrtf(df);
        g_invdeg[i] = 1.0f / df;
    }
}

// ---------------------------------------------------------------------------
// bin: atomic-free CSR placement. 8 edges/thread, loads batched for MLP.
#define BIN_BLOCKS 782   // ceil(EE/2048)
__global__ __launch_bounds__(256) void bin_kernel(const int* __restrict__ row,
                                                  const int* __restrict__ col) {
    int base = blockIdx.x * 2048 + threadIdx.x;
    int cs[8], rk[8], rw[8];
    #pragma unroll
    for (int u = 0; u < 8; u++) {
        int e = base + u * 256;
        if (e < EE) { cs[u] = col[e]; rk[u] = g_rank[e]; rw[u] = row[e]; }
        else cs[u] = -1;
    }
    int st[8];
    #pragma unroll
    for (int u = 0; u < 8; u++)
        if (cs[u] >= 0) st[u] = g_start[cs[u]];
    #pragma unroll
    for (int u = 0; u < 8; u++)
        if (cs[u] >= 0) g_csr[st[u] + rk[u]] = rw[u];
}

// ---------------------------------------------------------------------------
// gather: 8 threads per node; lane j owns fp16 columns 8j..8j+7 (one uint4).
// Software-pipelined: prefetch next chunk's csr+dinv while current chunk's
// y-row loads are in flight. Resets g_degi for the next call.
__global__ __launch_bounds__(256) void gather_kernel(const float* __restrict__ bias,
                                                     float4* __restrict__ out4) {
    int t = blockIdx.x * 256 + threadIdx.x;
    int c = t >> 3;
    if (c >= NN) return;
    int j = t & 7;

    int start = g_start[c];
    int cnt   = g_degi[c];
    if (j == 0) g_degi[c] = 0;

    const uint4* Y = (const uint4*)g_yh;   // row r -> Y[r*8 + j]

    float a0=0,a1=0,a2=0,a3=0,a4=0,a5=0,a6=0,a7=0;

    int nfull = cnt & ~3;
    int k = 0;
    if (nfull) {
        int s0 = g_csr[start],     s1 = g_csr[start + 1];
        int s2 = g_csr[start + 2], s3 = g_csr[start + 3];
        float w0 = g_dinv[s0], w1 = g_dinv[s1], w2 = g_dinv[s2], w3 = g_dinv[s3];
        while (true) {
            uint4 v0 = Y[s0 * 8 + j];
            uint4 v1 = Y[s1 * 8 + j];
            uint4 v2 = Y[s2 * 8 + j];
            uint4 v3 = Y[s3 * 8 + j];
            float ow0 = w0, ow1 = w1, ow2 = w2, ow3 = w3;
            int kn = k + 4;
            bool more = (kn + 4 <= nfull);
            if (more) {
                s0 = g_csr[start + kn];     s1 = g_csr[start + kn + 1];
                s2 = g_csr[start + kn + 2]; s3 = g_csr[start + kn + 3];
                w0 = g_dinv[s0]; w1 = g_dinv[s1]; w2 = g_dinv[s2]; w3 = g_dinv[s3];
            }
            {
                float2 p;
                p = __half22float2(*(__half2*)&v0.x); a0 += ow0*p.x; a1 += ow0*p.y;
                p = __half22float2(*(__half2*)&v0.y); a2 += ow0*p.x; a3 += ow0*p.y;
                p = __half22float2(*(__half2*)&v0.z); a4 += ow0*p.x; a5 += ow0*p.y;
                p = __half22float2(*(__half2*)&v0.w); a6 += ow0*p.x; a7 += ow0*p.y;
                p = __half22float2(*(__half2*)&v1.x); a0 += ow1*p.x; a1 += ow1*p.y;
                p = __half22float2(*(__half2*)&v1.y); a2 += ow1*p.x; a3 += ow1*p.y;
                p = __half22float2(*(__half2*)&v1.z); a4 += ow1*p.x; a5 += ow1*p.y;
                p = __half22float2(*(__half2*)&v1.w); a6 += ow1*p.x; a7 += ow1*p.y;
                p = __half22float2(*(__half2*)&v2.x); a0 += ow2*p.x; a1 += ow2*p.y;
                p = __half22float2(*(__half2*)&v2.y); a2 += ow2*p.x; a3 += ow2*p.y;
                p = __half22float2(*(__half2*)&v2.z); a4 += ow2*p.x; a5 += ow2*p.y;
                p = __half22float2(*(__half2*)&v2.w); a6 += ow2*p.x; a7 += ow2*p.y;
                p = __half22float2(*(__half2*)&v3.x); a0 += ow3*p.x; a1 += ow3*p.y;
                p = __half22float2(*(__half2*)&v3.y); a2 += ow3*p.x; a3 += ow3*p.y;
                p = __half22float2(*(__half2*)&v3.z); a4 += ow3*p.x; a5 += ow3*p.y;
                p = __half22float2(*(__half2*)&v3.w); a6 += ow3*p.x; a7 += ow3*p.y;
            }
            k = kn;
            if (!more) break;
        }
    }
    for (; k < cnt; k++) {
        int s = g_csr[start + k];
        float w = g_dinv[s];
        uint4 v = Y[s * 8 + j];
        float2 p;
        p = __half22float2(*(__half2*)&v.x); a0 += w*p.x; a1 += w*p.y;
        p = __half22float2(*(__half2*)&v.y); a2 += w*p.x; a3 += w*p.y;
        p = __half22float2(*(__half2*)&v.z); a4 += w*p.x; a5 += w*p.y;
        p = __half22float2(*(__half2*)&v.w); a6 += w*p.x; a7 += w*p.y;
    }

    float dc  = g_dinv[c];
    float inv = g_invdeg[c];
    uint4 sv = Y[c * 8 + j];
    const float4* b4 = (const float4*)bias;
    float4 ba = b4[2 * j], bb = b4[2 * j + 1];

    float2 p;
    float4 o0, o1;
    p = __half22float2(*(__half2*)&sv.x); o0.x = dc*a0 + inv*p.x + ba.x; o0.y = dc*a1 + inv*p.y + ba.y;
    p = __half22float2(*(__half2*)&sv.y); o0.z = dc*a2 + inv*p.x + ba.z; o0.w = dc*a3 + inv*p.y + ba.w;
    p = __half22float2(*(__half2*)&sv.z); o1.x = dc*a4 + inv*p.x + bb.x; o1.y = dc*a5 + inv*p.y + bb.y;
    p = __half22float2(*(__half2*)&sv.w); o1.z = dc*a6 + inv*p.x + bb.z; o1.w = dc*a7 + inv*p.y + bb.w;

    out4[c * 16 + 2 * j]     = o0;
    out4[c * 16 + 2 * j + 1] = o1;
}

// ---------------------------------------------------------------------------
extern "C" void kernel_launch(void* const* d_in, const int* in_sizes, int n_in,
                              void* d_out, int out_size) {
    const float* x  = nullptr;
    const int*   ei = nullptr;
    const float* Ww = nullptr;
    const float* Wb = nullptr;
    for (int i = 0; i < n_in; i++) {
        int sz = in_sizes[i];
        if (sz == 2 * EE)             ei = (const int*)d_in[i];
        else if (sz == DD * DD)       Ww = (const float*)d_in[i];
        else if (sz == DD)            Wb = (const float*)d_in[i];
        else if (sz == NN * DD && !x) x  = (const float*)d_in[i];
    }
    const int* row = ei;          // sources
    const int* col = ei + EE;     // targets
    float4* out4 = (float4*)d_out;

    fused_gemm_deg_kernel<<<GEMM_BLOCKS + DEG_BLOCKS, 256>>>(Ww, x, col);
    scan_kernel          <<<NB, 1024>>>();
    bin_kernel           <<<BIN_BLOCKS, 256>>>(row, col);
    gather_kernel        <<<(NN * 8 + 255) / 256, 256>>>(Wb, out4);
}